// round 14
// baseline (speedup 1.0000x reference)
#include <cuda_runtime.h>

#define MD 96
#define MN 9216

// wrap(v) = ((v+1) mod 2) - 1  ==  v - 2*floor(0.5*v + 0.5)   (3 instructions)
__device__ __forceinline__ float wrapf(float v) {
    return fmaf(-2.0f, floorf(fmaf(v, 0.5f, 0.5f)), v);
}

// ---------------------------------------------------------------------------
// Fully fused: grid 1024 = (t = b>>5) x (strip rs = b&31), 3 output rows each.
//   1. coefs + x-column staging
//   2. Gy/Gx diffs (nn-indexed layout) + tridiagonal Gram coefs
//   3. PT rows (branch-free gathers via padded coefs) + pts guard zeroing
//   4. 5-point stencil (branch-free via guard rows / pad column)
// ---------------------------------------------------------------------------
__global__ __launch_bounds__(256) void KF(const float* __restrict__ x,
                                          const float* __restrict__ DM,
                                          const float* __restrict__ DN,
                                          const float* __restrict__ eta,
                                          float* __restrict__ out) {
    __shared__ float dmd[96], dnd[96];
    __shared__ float dmuA[97], dnuA[97];   // slot 0 = zero pad; dmu[i] = dmuA[i+1]
    __shared__ float LdE[96], Nd[96];      // LdE = Ld + eta
    __shared__ float LuA[97], NuA[97];     // slot 0 = zero pad
    __shared__ float cor[4];
    __shared__ float xs[32 * 4 * 8];       // [(s*4+c)*8 + ri]
    __shared__ float gys[96 * 7];          // [nn*7 + (p - gyb)],  nn = s+32e
    __shared__ float gxs[96 * 5];          // [nn*5 + rowi]
    __shared__ float pts_phys[7 * 97];     // guard rows phys 0 & 6; data rows 1..5

    float* ptsd = pts_phys + 97;           // ptsd[row*97 + nn]

    int b   = blockIdx.x;
    int tid = threadIdx.x;
    int t   = b >> 5;
    int rs  = b & 31;
    int lo  = rs * 3;
    int prb = (lo > 0) ? lo - 1 : 0;
    int prt = (lo + 3 < 95) ? lo + 3 : 95;
    int gyb = (prb > 0) ? prb - 1 : 0;
    int gyt = prt;
    int xb  = gyb;
    int xt  = (gyt + 1 < 95) ? gyt + 1 : 95;
    int nx  = xt - xb + 1;                 // <= 7
    int ngy = gyt - gyb + 1;               // <= 6
    int npr = prt - prb + 1;               // 5 (4 for rs=0,31)
    int gshift = prb - gyb;                // 0 for rs=0, else 1
    int rowoff = lo - prb;                 // 0 for rs=0, else 1
    int s2  = 4 * (t & 7) + (t >> 3);
    float ev = eta[0];

    // ---- phase 1: bidiagonal coefs + corners + x columns ----
    if (tid < 96) {
        dmd[tid] = DM[tid * 97];
        dmuA[tid + 1] = (tid < 95) ? DM[tid * 97 + 1] : 0.f;
        dnd[tid] = DN[tid * 97];
        dnuA[tid + 1] = (tid < 95) ? DN[tid * 97 + 1] : 0.f;
    } else if (tid == 96) {
        cor[0] = DM[95 * MD + 94];
        cor[1] = DM[95 * MD + 95];
        cor[2] = DN[95 * MD + 94];
        cor[3] = DN[95 * MD + 95];
        dmuA[0] = 0.f; dnuA[0] = 0.f; LuA[0] = 0.f; NuA[0] = 0.f;
    }
    // x[s][xb+ri][3t+c]; c fastest in lane order (good sectors)
#pragma unroll
    for (int k = 0; k < 4; k++) {
        int idx = tid + k * 256;
        int c  = idx & 3;
        int ri = (idx >> 2) & 7;
        int s  = idx >> 5;
        int col = 3 * t + c;
        if (ri < nx && col < MD)
            xs[(s * 4 + c) * 8 + ri] = x[s * MN + (xb + ri) * MD + col];
    }
    __syncthreads();

    // ---- phase 2: Gram tridiagonal coefs + Gy/Gx diffs ----
    if (tid < 96) {
        int i = tid;
        float dmu_im1 = dmuA[i];           // dmu[i-1] (pad at i=0)
        float a = dmd[i] * dmd[i] + dmu_im1 * dmu_im1;
        if (i == 94) a += cor[0] * cor[0];
        LdE[i] = a + ev;
        LuA[i + 1] = (i < 95) ? dmd[i] * dmuA[i + 1] + ((i == 94) ? cor[0] * cor[1] : 0.f) : 0.f;
        float dnu_im1 = dnuA[i];
        float n = dnd[i] * dnd[i] + dnu_im1 * dnu_im1;
        if (i == 94) n += cor[2] * cor[2];
        Nd[i] = n;
        NuA[i + 1] = (i < 95) ? dnd[i] * dnuA[i + 1] + ((i == 94) ? cor[2] * cor[3] : 0.f) : 0.f;
    }
#pragma unroll
    for (int k = 0; k < 3; k++) {
        int idx = tid + k * 256;           // < 768
        int pi = idx & 7;
        int w  = idx >> 3;                 // nn = s + 32e
        int s  = w & 31;
        int e  = w >> 5;
        const float* xc = xs + (s * 4 + e) * 8;
        // Gy (x row index == pi since xb == gyb)
        if (pi < ngy) {
            int p = gyb + pi;
            float v;
            if (p < 95) v = dmd[p] * xc[pi] + dmuA[p + 1] * xc[pi + 1];
            else        v = cor[0] * xc[94 - xb] + cor[1] * xc[95 - xb];
            gys[w * 7 + pi] = wrapf(v);
        }
        // Gx
        if (pi < npr) {
            int c  = 3 * t + e;
            int ri = pi + gshift;
            float v;
            if (c < 95) v = dnd[c] * xc[ri] + dnuA[c + 1] * xc[8 + ri];
            else        v = cor[2] * xs[(s * 4 + 1) * 8 + ri]
                          + cor[3] * xs[(s * 4 + 2) * 8 + ri];   // t=31, e=2
            gxs[w * 5 + pi] = wrapf(v);
        }
    }
    __syncthreads();

    // ---- phase 3: PT rows + guard zeroing ----
    // guards: phys row 0, phys row 6, pad col of data rows, and (edge strips) row npr
    if (tid < 97) pts_phys[tid] = 0.f;
    else if (tid < 194) pts_phys[6 * 97 + tid - 97] = 0.f;
    else if (tid < 199) ptsd[(tid - 194) * 97 + 96] = 0.f;
    else if (tid < 296 && npr == 4) ptsd[4 * 97 + (tid - 199)] = 0.f;

    int nwork3 = npr * 96;
    int g95 = 95 - gyb;
#pragma unroll
    for (int k = 0; k < 2; k++) {
        int idx = tid + k * 256;
        if (idx < nwork3) {
            int rowi = idx / 96;
            int nn   = idx - rowi * 96;
            int mm   = prb + rowi;
            int ri2  = rowi + gshift;
            int ri1  = (ri2 > 0) ? ri2 - 1 : 0;
            const float* gyn = gys + nn * 7;
            float h = dmuA[mm] * gyn[ri1] + dmd[mm] * gyn[ri2];
            if (mm == 94) h += cor[0] * gyn[g95];
            int q1 = (nn > 0) ? nn - 1 : 0;
            float t2 = dnuA[nn] * gxs[q1 * 5 + rowi] + dnd[nn] * gxs[nn * 5 + rowi];
            if (nn == 94) t2 += cor[2] * gxs[95 * 5 + rowi];
            ptsd[rowi * 97 + nn] = h + t2 + ev * x[s2 * MN + mm * MD + nn];
        }
    }
    __syncthreads();

    // ---- phase 4: branch-free 5-point stencil ----
#pragma unroll
    for (int k = 0; k < 2; k++) {
        int idx = tid + k * 256;           // < 288
        if (idx < 3 * MD) {
            int di = idx / 96;
            int ni = idx - di * 96;
            int mi = lo + di;
            int row = di + rowoff;
            const float* pr = ptsd + row * 97 + ni;
            float v = (LdE[mi] + Nd[ni]) * pr[0]
                    + LuA[mi]     * pr[-97]
                    + LuA[mi + 1] * pr[97]
                    + NuA[ni]     * pr[-1]
                    + NuA[ni + 1] * pr[1];
            out[s2 * MN + mi * MD + ni] = v;
        }
    }
}

// ---------------------------------------------------------------------------
extern "C" void kernel_launch(void* const* d_in, const int* in_sizes, int n_in,
                              void* d_out, int out_size) {
    // inputs: x(294912), eta(1), A_w(84934656, unused), DM(9216), DN(9216)
    int ix = 0, ie = 1, idm = 3, idn = 4;
    {
        int found_d = 0;
        for (int i = 0; i < n_in; i++) {
            if (in_sizes[i] == 294912) ix = i;
            else if (in_sizes[i] == 1) ie = i;
            else if (in_sizes[i] == 9216) {
                if (found_d == 0) { idm = i; found_d = 1; }
                else idn = i;
            }
        }
    }
    const float* x   = (const float*)d_in[ix];
    const float* eta = (const float*)d_in[ie];
    const float* DM  = (const float*)d_in[idm];
    const float* DN  = (const float*)d_in[idn];
    float* out = (float*)d_out;

    KF<<<1024, 256>>>(x, DM, DN, eta, out);
}

// round 15
// speedup vs baseline: 1.3851x; 1.3851x over previous
#include <cuda_runtime.h>

#define MD 96
#define MN 9216

// wrap(v) = ((v+1) mod 2) - 1  ==  v - 2*floor(0.5*v + 0.5)   (3 instructions,
// matches Python mod semantics: floor-based, divisor-signed)
__device__ __forceinline__ float wrapf(float v) {
    return fmaf(-2.0f, floorf(fmaf(v, 0.5f, 0.5f)), v);
}

// ---------------------------------------------------------------------------
// Fully fused: grid 1024 = (t = b>>5) x (strip rs = b&31), 3 output rows each.
// Phases (all in smem):
//   1. coefs + x-column staging + phase-3 x prefetch (registers)
//   2. Gy/Gx column diffs + tridiagonal Gram coefs
//   3. PT rows [prb..prt] (1-row halo each side)
//   4. 5-point stencil -> out
// ---------------------------------------------------------------------------
__global__ __launch_bounds__(256) void KF(const float* __restrict__ x,
                                          const float* __restrict__ DM,
                                          const float* __restrict__ DN,
                                          const float* __restrict__ eta,
                                          float* __restrict__ out) {
    __shared__ float dmd[96], dmu[96], dnd[96], dnu[96];
    __shared__ float Ld[96], Lu[96], Nd[96], Nu[96];
    __shared__ float cor[4];
    __shared__ float xs [32 * 4 * 10];   // [(s*4+c)*10 + ri]  pitch 10: conflict-free
    __shared__ float gys[96 * 9];        // [(s*3+e)*9 + (p-gyb)]
    __shared__ float gxs[96 * 9];        // [(s*3+e)*9 + (mm-prb)]
    __shared__ float pts[5 * 97];        // [(mm-prb)*97 + nn]

    int b   = blockIdx.x;
    int tid = threadIdx.x;
    int t   = b >> 5;
    int rs  = b & 31;
    int lo  = rs * 3;
    int prb = (lo > 0) ? lo - 1 : 0;
    int prt = (lo + 3 < 95) ? lo + 3 : 95;
    int gyb = (prb > 0) ? prb - 1 : 0;
    int gyt = prt;
    int xb  = gyb;
    int xt  = (gyt + 1 < 95) ? gyt + 1 : 95;
    int nx  = xt - xb + 1;                // <= 7
    int ngy = gyt - gyb + 1;              // <= 6
    int npr = prt - prb + 1;              // <= 5
    int s2  = 4 * (t & 7) + (t >> 3);

    // ---- phase 1: coefs + x columns + phase-3 prefetch ----
    if (tid < 96) {
        dmd[tid] = DM[tid * 97];
        dmu[tid] = (tid < 95) ? DM[tid * 97 + 1] : 0.f;
        dnd[tid] = DN[tid * 97];
        dnu[tid] = (tid < 95) ? DN[tid * 97 + 1] : 0.f;
    } else if (tid == 96) {
        cor[0] = DM[95 * MD + 94];
        cor[1] = DM[95 * MD + 95];
        cor[2] = DN[95 * MD + 94];
        cor[3] = DN[95 * MD + 95];
    }
    // x[s][xb+ri][3t+c]; c fastest in lane order (contiguous 16B per 4 lanes)
#pragma unroll
    for (int k = 0; k < 4; k++) {
        int idx = tid + k * 256;
        int c  = idx & 3;
        int ri = (idx >> 2) & 7;
        int s  = idx >> 5;
        int col = 3 * t + c;
        if (ri < nx && col < MD)
            xs[(s * 4 + c) * 10 + ri] = x[s * MN + (xb + ri) * MD + col];
    }
    // prefetch the phase-3 epilogue x values (indices depend only on b, tid)
    float px[2];
#pragma unroll
    for (int k = 0; k < 2; k++) {
        int idx = tid + k * 256;
        int rowi = idx / 96;
        int nn   = idx - rowi * 96;
        px[k] = (rowi < npr) ? x[s2 * MN + (prb + rowi) * MD + nn] : 0.f;
    }
    __syncthreads();

    // ---- phase 2: Gram tridiagonal coefs + Gy/Gx diffs ----
    if (tid < 96) {
        int i = tid;
        float a = dmd[i] * dmd[i];
        if (i >= 1)  a += dmu[i - 1] * dmu[i - 1];
        if (i == 94) a += cor[0] * cor[0];
        Ld[i] = a;
        Lu[i] = (i < 95) ? dmd[i] * dmu[i] + ((i == 94) ? cor[0] * cor[1] : 0.f) : 0.f;
        float n = dnd[i] * dnd[i];
        if (i >= 1)  n += dnu[i - 1] * dnu[i - 1];
        if (i == 94) n += cor[2] * cor[2];
        Nd[i] = n;
        Nu[i] = (i < 95) ? dnd[i] * dnu[i] + ((i == 94) ? cor[2] * cor[3] : 0.f) : 0.f;
    }
#pragma unroll
    for (int k = 0; k < 3; k++) {
        int idx = tid + k * 256;          // < 768
        int pi = idx & 7;
        int u  = idx >> 3;                // s*3+e, 0..95
        int s  = u / 3;
        int e  = u - 3 * s;
        const float* xc = xs + (s * 4 + e) * 10;
        // Gy (x row index == pi since xb == gyb)
        if (pi < ngy) {
            int p = gyb + pi;
            float v;
            if (p < 95) v = dmd[p] * xc[pi] + dmu[p] * xc[pi + 1];
            else        v = cor[0] * xc[94 - xb] + cor[1] * xc[95 - xb];
            gys[u * 9 + pi] = wrapf(v);
        }
        // Gx
        if (pi < npr) {
            int mm = prb + pi;
            int c  = 3 * t + e;
            int ri = mm - xb;
            float v;
            if (c < 95) v = dnd[c] * xc[ri] + dnu[c] * xc[10 + ri];
            else        v = cor[2] * xs[(s * 4 + 1) * 10 + ri]
                          + cor[3] * xs[(s * 4 + 2) * 10 + ri];   // t=31, e=2
            gxs[u * 9 + pi] = wrapf(v);
        }
    }
    __syncthreads();

    // ---- phase 3: PT rows [prb..prt] ----
    float ev = eta[0];
#pragma unroll
    for (int k = 0; k < 2; k++) {
        int idx = tid + k * 256;          // < 480
        int rowi = idx / 96;
        int nn   = idx - rowi * 96;
        if (rowi < npr) {
            int mm = prb + rowi;
            // H term: col mm of DM applied to Gy col (nn&31, nn>>5)
            const float* gy = gys + ((nn & 31) * 3 + (nn >> 5)) * 9;
            float h = 0.f;
            if (mm >= 1)  h += dmu[mm - 1] * gy[mm - 1 - gyb];
            if (mm < 95)  h += dmd[mm] * gy[mm - gyb];
            if (mm == 94) h += cor[0] * gy[95 - gyb];
            if (mm == 95) h += cor[1] * gy[95 - gyb];
            // DN^T term: col nn of DN across q -> Gx rows
            float t2 = 0.f;
            if (nn >= 1) {
                int q = nn - 1;
                t2 += dnu[q] * gxs[((q & 31) * 3 + (q >> 5)) * 9 + rowi];
            }
            if (nn < 95)  t2 += dnd[nn] * gxs[((nn & 31) * 3 + (nn >> 5)) * 9 + rowi];
            if (nn == 94) t2 += cor[2] * gxs[(31 * 3 + 2) * 9 + rowi];
            if (nn == 95) t2 += cor[3] * gxs[(31 * 3 + 2) * 9 + rowi];
            pts[rowi * 97 + nn] = h + t2 + ev * px[k];
        }
    }
    __syncthreads();

    // ---- phase 4: 5-point stencil, coalesced store ----
#pragma unroll
    for (int k = 0; k < 2; k++) {
        int idx = tid + k * 256;          // < 288
        if (idx < 3 * MD) {
            int di = idx / 96;
            int mi = lo + di;
            int ni = idx - di * 96;
            int row = mi - prb;
            float c = pts[row * 97 + ni];
            float v = (Ld[mi] + Nd[ni] + ev) * c;
            if (mi > 0)  v += Lu[mi - 1] * pts[(row - 1) * 97 + ni];
            if (mi < 95) v += Lu[mi]     * pts[(row + 1) * 97 + ni];
            if (ni > 0)  v += Nu[ni - 1] * pts[row * 97 + ni - 1];
            if (ni < 95) v += Nu[ni]     * pts[row * 97 + ni + 1];
            out[s2 * MN + mi * MD + ni] = v;
        }
    }
}

// ---------------------------------------------------------------------------
extern "C" void kernel_launch(void* const* d_in, const int* in_sizes, int n_in,
                              void* d_out, int out_size) {
    // inputs: x(294912), eta(1), A_w(84934656, unused), DM(9216), DN(9216)
    int ix = 0, ie = 1, idm = 3, idn = 4;
    {
        int found_d = 0;
        for (int i = 0; i < n_in; i++) {
            if (in_sizes[i] == 294912) ix = i;
            else if (in_sizes[i] == 1) ie = i;
            else if (in_sizes[i] == 9216) {
                if (found_d == 0) { idm = i; found_d = 1; }
                else idn = i;
            }
        }
    }
    const float* x   = (const float*)d_in[ix];
    const float* eta = (const float*)d_in[ie];
    const float* DM  = (const float*)d_in[idm];
    const float* DN  = (const float*)d_in[idn];
    float* out = (float*)d_out;

    KF<<<1024, 256>>>(x, DM, DN, eta, out);
}